// round 3
// baseline (speedup 1.0000x reference)
#include <cuda_runtime.h>

// ---------------------------------------------------------------------------
// SparseNeuralNetwork: 256 independent 1->16->8->1 micro-MLPs.
//   out[b,o] = b2[o] + sum_i MLP_{i,o}(x[b,i])
// Strategy: compact nonzero weights -> smem; warp = output o, lane = sample
// pair; packed fp32 (fma.rn.f32x2) over adjacent hidden units. Weight packs
// loaded directly as ulonglong2 (no pack movs); split accumulators shorten
// the L1 chain; i-loop unrolled x2 for cross-iteration ILP.
// ---------------------------------------------------------------------------

typedef unsigned long long ull;

__device__ float g_w0[4096];
__device__ float g_w1[32768];
__device__ float g_w2[2048];

__global__ void gather_kernel(const float* __restrict__ W0,
                              const float* __restrict__ W1,
                              const float* __restrict__ W2) {
    int t = blockIdx.x * blockDim.x + threadIdx.x;
    if (t < 4096) g_w0[t] = W0[t * 16 + (t >> 8)];
    if (t < 2048) g_w2[t] = W2[((t >> 3) & 15) * 2048 + t];
    if (t < 32768) {
        int r = t >> 4;
        int k = t & 15;
        g_w1[t] = W1[r * 4096 + (r >> 3) * 16 + k];
    }
}

// ---- packed f32x2 helpers --------------------------------------------------
__device__ __forceinline__ ull pk2(float lo, float hi) {
    ull r;
    asm("mov.b64 %0, {%1, %2};" : "=l"(r) : "f"(lo), "f"(hi));
    return r;
}
__device__ __forceinline__ void up2(ull v, float& lo, float& hi) {
    asm("mov.b64 {%0, %1}, %2;" : "=f"(lo), "=f"(hi) : "l"(v));
}
__device__ __forceinline__ ull fma2(ull a, ull b, ull c) {
    ull d;
    asm("fma.rn.f32x2 %0, %1, %2, %3;" : "=l"(d) : "l"(a), "l"(b), "l"(c));
    return d;
}
__device__ __forceinline__ ull add2(ull a, ull b) {
    ull d;
    asm("add.rn.f32x2 %0, %1, %2;" : "=l"(d) : "l"(a), "l"(b));
    return d;
}
__device__ __forceinline__ ull relu2(ull v) {
    float a, b;
    up2(v, a, b);
    a = fmaxf(a, 0.0f);
    b = fmaxf(b, 0.0f);
    return pk2(a, b);
}

// Shared memory layout (floats):
//   sw1 [32768]  layer1 weights, row-major (16 per y1-unit)
//   sw0 [ 4096]  layer0 weights
//   sb0 [ 4096]  layer0 bias
//   sb1 [ 2048]  layer1 bias
//   sw2 [ 2048]  layer2 weights (indexed by y1 row)
//   sx  [ 1056]  x chunk transposed [16][66]
constexpr int SMEM_FLOATS = 32768 + 4096 + 4096 + 2048 + 2048 + 1056;
constexpr int SMEM_BYTES  = SMEM_FLOATS * 4;   // 184448 B

__global__ __launch_bounds__(512, 1)
void mlp_kernel(const float* __restrict__ x,
                const float* __restrict__ b0,
                const float* __restrict__ b1,
                const float* __restrict__ b2,
                float* __restrict__ out,
                int n) {
    extern __shared__ float smem[];
    float* sw1 = smem;
    float* sw0 = sw1 + 32768;
    float* sb0 = sw0 + 4096;
    float* sb1 = sb0 + 4096;
    float* sw2 = sb1 + 2048;
    float* sx  = sw2 + 2048;

    const int tid  = threadIdx.x;
    const int o    = tid >> 5;   // warp index = output neuron
    const int lane = tid & 31;   // lane = sample-pair index

    // ---- Stage compacted weights/biases into shared memory (float4) -------
    {
        const float4* s;
        float4* d;
        s = (const float4*)g_w1; d = (float4*)sw1;
        for (int idx = tid; idx < 32768 / 4; idx += 512) d[idx] = s[idx];
        s = (const float4*)g_w0; d = (float4*)sw0;
        for (int idx = tid; idx < 4096 / 4; idx += 512) d[idx] = s[idx];
        s = (const float4*)b0;   d = (float4*)sb0;
        for (int idx = tid; idx < 4096 / 4; idx += 512) d[idx] = s[idx];
        s = (const float4*)b1;   d = (float4*)sb1;
        for (int idx = tid; idx < 2048 / 4; idx += 512) d[idx] = s[idx];
        s = (const float4*)g_w2; d = (float4*)sw2;
        for (int idx = tid; idx < 2048 / 4; idx += 512) d[idx] = s[idx];
    }

    // ---- Stage x chunk transposed: sx[i*66 + s] = x[(base+s)*16 + i] -------
    const int base = blockIdx.x * 64;
    for (int e = tid; e < 1024; e += 512) {
        int s = e >> 4, i = e & 15;
        float v = (base + s < n) ? x[(base + s) * 16 + i] : 0.0f;
        sx[i * 66 + s] = v;
    }
    __syncthreads();

    float outl = 0.0f, outh = 0.0f;   // per-sample output accumulators

    #pragma unroll 2
    for (int i = 0; i < 16; ++i) {
        const float2 xp = *(const float2*)(sx + i * 66 + 2 * lane);
        const ull xpl = pk2(xp.x, xp.x);
        const ull xph = pk2(xp.y, xp.y);

        const int base0 = (i << 8) + (o << 4);   // i*256 + o*16
        const int g8    = base0 >> 1;            // (i*16+o)*8

        // ---- layer 0: 16 units as 8 k-packs, both samples -----------------
        ull y0a[8], y0b[8];
        {
            const ulonglong2* w2p = (const ulonglong2*)(sw0 + base0);
            const ulonglong2* c2p = (const ulonglong2*)(sb0 + base0);
            #pragma unroll
            for (int q = 0; q < 4; ++q) {
                ulonglong2 w = w2p[q], c = c2p[q];
                y0a[2 * q + 0] = relu2(fma2(w.x, xpl, c.x));
                y0a[2 * q + 1] = relu2(fma2(w.y, xpl, c.y));
                y0b[2 * q + 0] = relu2(fma2(w.x, xph, c.x));
                y0b[2 * q + 1] = relu2(fma2(w.y, xph, c.y));
            }
        }

        // preload layer1 biases + layer2 weights for the 8 y1 units ---------
        float b1r[8], w2r[8];
        {
            const float4* bb = (const float4*)(sb1 + g8);
            const float4* ww = (const float4*)(sw2 + g8);
            float4 t0 = bb[0], t1 = bb[1];
            b1r[0] = t0.x; b1r[1] = t0.y; b1r[2] = t0.z; b1r[3] = t0.w;
            b1r[4] = t1.x; b1r[5] = t1.y; b1r[6] = t1.z; b1r[7] = t1.w;
            t0 = ww[0]; t1 = ww[1];
            w2r[0] = t0.x; w2r[1] = t0.y; w2r[2] = t0.z; w2r[3] = t0.w;
            w2r[4] = t1.x; w2r[5] = t1.y; w2r[6] = t1.z; w2r[7] = t1.w;
        }

        // ---- layer 1 (+ relu + layer 2 fold), 8 y1 units ------------------
        const ull z = 0;
        #pragma unroll
        for (int j = 0; j < 8; ++j) {
            const ulonglong2* rp = (const ulonglong2*)(sw1 + ((g8 + j) << 4));
            ulonglong2 p0 = rp[0], p1 = rp[1], p2 = rp[2], p3 = rp[3];

            // sample 0: two 4-deep chains
            {
                ull aA = fma2(p0.x, y0a[0], z);
                ull aB = fma2(p0.y, y0a[1], z);
                aA = fma2(p1.x, y0a[2], aA);
                aB = fma2(p1.y, y0a[3], aB);
                aA = fma2(p2.x, y0a[4], aA);
                aB = fma2(p2.y, y0a[5], aB);
                aA = fma2(p3.x, y0a[6], aA);
                aB = fma2(p3.y, y0a[7], aB);
                ull acc = add2(aA, aB);
                float al, ah;
                up2(acc, al, ah);
                float s = al + ah + b1r[j];
                outl = fmaf(w2r[j], fmaxf(s, 0.0f), outl);
            }
            // sample 1
            {
                ull aA = fma2(p0.x, y0b[0], z);
                ull aB = fma2(p0.y, y0b[1], z);
                aA = fma2(p1.x, y0b[2], aA);
                aB = fma2(p1.y, y0b[3], aB);
                aA = fma2(p2.x, y0b[4], aA);
                aB = fma2(p2.y, y0b[5], aB);
                aA = fma2(p3.x, y0b[6], aA);
                aB = fma2(p3.y, y0b[7], aB);
                ull acc = add2(aA, aB);
                float al, ah;
                up2(acc, al, ah);
                float s = al + ah + b1r[j];
                outh = fmaf(w2r[j], fmaxf(s, 0.0f), outh);
            }
        }
    }

    // ---- write outputs -----------------------------------------------------
    const float bb = __ldg(&b2[o]);
    const int s0 = base + 2 * lane;
    const int s1 = s0 + 1;
    if (s0 < n) out[s0 * 16 + o] = outl + bb;
    if (s1 < n) out[s1 * 16 + o] = outh + bb;
}

extern "C" void kernel_launch(void* const* d_in, const int* in_sizes, int n_in,
                              void* d_out, int out_size) {
    const float *x = nullptr, *W0 = nullptr, *b0 = nullptr, *W1 = nullptr;
    const float *b1 = nullptr, *W2 = nullptr, *b2 = nullptr;
    for (int idx = 0; idx < n_in; ++idx) {
        switch (in_sizes[idx]) {
            case 131072:  x  = (const float*)d_in[idx]; break;   // [8192,16]
            case 65536:   W0 = (const float*)d_in[idx]; break;   // [4096,16]
            case 4096:    b0 = (const float*)d_in[idx]; break;
            case 8388608: W1 = (const float*)d_in[idx]; break;   // [2048,4096]
            case 2048:    b1 = (const float*)d_in[idx]; break;
            case 32768:   W2 = (const float*)d_in[idx]; break;   // [16,2048]
            case 16:      b2 = (const float*)d_in[idx]; break;
            default: break;
        }
    }

    const int n = out_size / 16;

    gather_kernel<<<128, 256>>>(W0, W1, W2);

    cudaFuncSetAttribute(mlp_kernel,
                         cudaFuncAttributeMaxDynamicSharedMemorySize, SMEM_BYTES);
    const int blocks = (n + 63) / 64;
    mlp_kernel<<<blocks, 512, SMEM_BYTES>>>(x, b0, b1, b2, (float*)d_out, n);
}

// round 4
// speedup vs baseline: 1.0099x; 1.0099x over previous
#include <cuda_runtime.h>

// ---------------------------------------------------------------------------
// SparseNeuralNetwork: 256 independent 1->16->8->1 micro-MLPs.
//   out[b,o] = b2[o] + sum_i MLP_{i,o}(x[b,i])
//
// This version packs f32x2 over SAMPLE PAIRS (weights pre-duplicated in smem),
// eliminating all horizontal reductions. k-outer accumulation keeps y0 in ~4
// regs, total ~70 regs -> 3 blocks/SM (24 warps). Work split: block = 8 warps
// (8 outputs, o-half) x i-quarter (4 inputs) x 128 samples (4/thread).
// Partial sums over i-quarters combine via atomicAdd; out preset to b2.
// ---------------------------------------------------------------------------

typedef unsigned long long ull;

// Duplicated compact weights (each scalar stored twice for f32x2 operands).
__device__ float g_w0d[8192];    // [io(256)][k(16)][2]
__device__ float g_b0d[8192];    // [io][k][2]
__device__ float g_w1d[65536];   // [io][k(16)][j(8)][2]
__device__ float g_b1d[4096];    // [io][j(8)][2]
__device__ float g_w2d[4096];    // [io][j(8)][2]

__global__ void gather_kernel(const float* __restrict__ W0,
                              const float* __restrict__ b0,
                              const float* __restrict__ W1,
                              const float* __restrict__ b1,
                              const float* __restrict__ W2,
                              const float* __restrict__ b2,
                              float* __restrict__ out,
                              int out_elems) {
    int t = blockIdx.x * blockDim.x + threadIdx.x;
    if (t < out_elems) out[t] = b2[t & 15];          // preset out = b2[o]
    if (t < 65536) {                                  // w1 dup: [io][k][j][2]
        int j  = (t >> 1) & 7;
        int k  = (t >> 4) & 15;
        int io = t >> 8;
        int r  = io * 8 + j;
        g_w1d[t] = W1[r * 4096 + io * 16 + k];
    }
    if (t < 8192) {                                   // w0/b0 dup: [io][k][2]
        int k  = (t >> 1) & 15;
        int io = t >> 5;
        int r  = io * 16 + k;
        int i  = io >> 4;
        g_w0d[t] = W0[r * 16 + i];
        g_b0d[t] = b0[r];
    }
    if (t < 4096) {                                   // b1/w2 dup: [io][j][2]
        int j  = (t >> 1) & 7;
        int io = t >> 4;
        int r  = io * 8 + j;
        g_b1d[t] = b1[r];
        g_w2d[t] = W2[(io & 15) * 2048 + r];
    }
}

// ---- packed f32x2 helpers --------------------------------------------------
__device__ __forceinline__ ull pk2(float lo, float hi) {
    ull r;
    asm("mov.b64 %0, {%1, %2};" : "=l"(r) : "f"(lo), "f"(hi));
    return r;
}
__device__ __forceinline__ void up2(ull v, float& lo, float& hi) {
    asm("mov.b64 {%0, %1}, %2;" : "=f"(lo), "=f"(hi) : "l"(v));
}
__device__ __forceinline__ ull fma2(ull a, ull b, ull c) {
    ull d;
    asm("fma.rn.f32x2 %0, %1, %2, %3;" : "=l"(d) : "l"(a), "l"(b), "l"(c));
    return d;
}
__device__ __forceinline__ ull relu2(ull v) {
    float a, b;
    up2(v, a, b);
    a = fmaxf(a, 0.0f);
    b = fmaxf(b, 0.0f);
    return pk2(a, b);
}

// ---------------------------------------------------------------------------
// mlp kernel: blockIdx.x encodes (chunk, i-quarter, o-half):
//   oh = b & 1, iq = (b>>1) & 3, chunk = b >> 3
// block = 256 threads = 8 warps; warp -> output o = oh*8 + warp;
// lane handles 4 samples (2 f32x2 packs), chunk = 128 samples.
// ---------------------------------------------------------------------------
__global__ __launch_bounds__(256, 3)
void mlp_kernel(const float* __restrict__ x,
                float* __restrict__ out,
                int n) {
    __shared__ float sw1d[8192];   // [ii(4)][oo(8)][k(16)][j(8)][2]
    __shared__ float sw0d[1024];   // [ii][oo][k][2]
    __shared__ float sb0d[1024];
    __shared__ float sb1d[512];    // [ii][oo][j][2]
    __shared__ float sw2d[512];
    __shared__ float sx[512];      // [ii][128 samples]

    const int tid  = threadIdx.x;
    const int w    = tid >> 5;
    const int lane = tid & 31;

    const int bidx  = blockIdx.x;
    const int oh    = bidx & 1;
    const int iq    = (bidx >> 1) & 3;
    const int chunk = bidx >> 3;
    const int base  = chunk * 128;

    // ---- stage duplicated weight slices (contiguous per ii) ---------------
    #pragma unroll
    for (int ii = 0; ii < 4; ++ii) {
        const int i   = iq * 4 + ii;
        const int gio = i * 16 + oh * 8;   // first (i,o) of this block's slice
        {
            const float4* s = (const float4*)(g_w1d + gio * 256);
            float4* d = (float4*)(sw1d + ii * 2048);
            for (int t = tid; t < 512; t += 256) d[t] = s[t];
        }
        if (tid < 64) {
            ((float4*)(sw0d + ii * 256))[tid] = ((const float4*)(g_w0d + gio * 32))[tid];
            ((float4*)(sb0d + ii * 256))[tid] = ((const float4*)(g_b0d + gio * 32))[tid];
        }
        if (tid < 32) {
            ((float4*)(sb1d + ii * 128))[tid] = ((const float4*)(g_b1d + gio * 16))[tid];
            ((float4*)(sw2d + ii * 128))[tid] = ((const float4*)(g_w2d + gio * 16))[tid];
        }
    }
    // x transposed: sx[ii][s] = x[(base+s)*16 + (iq*4+ii)]
    for (int e = tid; e < 512; e += 256) {
        int ii = e >> 7, s = e & 127;
        int gs = base + s;
        sx[ii * 128 + s] = (gs < n) ? x[gs * 16 + (iq * 4 + ii)] : 0.0f;
    }
    __syncthreads();

    ull outp0 = 0, outp1 = 0;   // packed outputs: (s0,s1) and (s2,s3)

    #pragma unroll 1
    for (int ii = 0; ii < 4; ++ii) {
        const int bio = ii * 8 + w;   // local (ii, oo) slot

        // x packs: 4 consecutive samples -> (s0,s1), (s2,s3), zero movs
        const ulonglong2 xp = *(const ulonglong2*)(sx + ii * 128 + 4 * lane);

        // accumulators init = b1 (duplicated), one set per sample pack
        ull acc0[8], acc1[8];
        {
            const ulonglong2* bp = (const ulonglong2*)(sb1d + bio * 16);
            #pragma unroll
            for (int q = 0; q < 4; ++q) {
                ulonglong2 v = bp[q];
                acc0[2 * q] = v.x; acc0[2 * q + 1] = v.y;
            }
            #pragma unroll
            for (int q = 0; q < 4; ++q) {
                ulonglong2 v = bp[q];
                acc1[2 * q] = v.x; acc1[2 * q + 1] = v.y;
            }
        }

        const float* w0base = sw0d + bio * 32;
        const float* b0base = sb0d + bio * 32;
        const float* w1base = sw1d + bio * 256;

        #pragma unroll
        for (int k2 = 0; k2 < 8; ++k2) {
            // layer 0 for k = 2*k2 and 2*k2+1 (dup weights, packed samples)
            const ulonglong2 w0p = *(const ulonglong2*)(w0base + k2 * 4);
            const ulonglong2 b0p = *(const ulonglong2*)(b0base + k2 * 4);
            const ull y00 = relu2(fma2(w0p.x, xp.x, b0p.x));  // k,   pack01
            const ull y01 = relu2(fma2(w0p.x, xp.y, b0p.x));  // k,   pack23
            const ull y10 = relu2(fma2(w0p.y, xp.x, b0p.y));  // k+1, pack01
            const ull y11 = relu2(fma2(w0p.y, xp.y, b0p.y));  // k+1, pack23

            // layer 1 scatter: k row (8 dup weights over j)
            {
                const ulonglong2* w1p = (const ulonglong2*)(w1base + (2 * k2) * 16);
                #pragma unroll
                for (int q = 0; q < 4; ++q) {
                    ulonglong2 v = w1p[q];
                    acc0[2 * q]     = fma2(v.x, y00, acc0[2 * q]);
                    acc1[2 * q]     = fma2(v.x, y01, acc1[2 * q]);
                    acc0[2 * q + 1] = fma2(v.y, y00, acc0[2 * q + 1]);
                    acc1[2 * q + 1] = fma2(v.y, y01, acc1[2 * q + 1]);
                }
            }
            // k+1 row
            {
                const ulonglong2* w1p = (const ulonglong2*)(w1base + (2 * k2 + 1) * 16);
                #pragma unroll
                for (int q = 0; q < 4; ++q) {
                    ulonglong2 v = w1p[q];
                    acc0[2 * q]     = fma2(v.x, y10, acc0[2 * q]);
                    acc1[2 * q]     = fma2(v.x, y11, acc1[2 * q]);
                    acc0[2 * q + 1] = fma2(v.y, y10, acc0[2 * q + 1]);
                    acc1[2 * q + 1] = fma2(v.y, y11, acc1[2 * q + 1]);
                }
            }
        }

        // relu + layer-2 fold (still packed over samples; no horizontal!)
        {
            const ulonglong2* w2p = (const ulonglong2*)(sw2d + bio * 16);
            #pragma unroll
            for (int q = 0; q < 4; ++q) {
                ulonglong2 v = w2p[q];
                outp0 = fma2(v.x, relu2(acc0[2 * q]), outp0);
                outp1 = fma2(v.x, relu2(acc1[2 * q]), outp1);
                outp0 = fma2(v.y, relu2(acc0[2 * q + 1]), outp0);
                outp1 = fma2(v.y, relu2(acc1[2 * q + 1]), outp1);
            }
        }
    }

    // ---- combine i-quarter partials via atomics ----------------------------
    float v0, v1, v2, v3;
    up2(outp0, v0, v1);
    up2(outp1, v2, v3);
    const int o  = oh * 8 + w;
    const int s0 = base + 4 * lane;
    if (s0 + 0 < n) atomicAdd(out + (s0 + 0) * 16 + o, v0);
    if (s0 + 1 < n) atomicAdd(out + (s0 + 1) * 16 + o, v1);
    if (s0 + 2 < n) atomicAdd(out + (s0 + 2) * 16 + o, v2);
    if (s0 + 3 < n) atomicAdd(out + (s0 + 3) * 16 + o, v3);
}

extern "C" void kernel_launch(void* const* d_in, const int* in_sizes, int n_in,
                              void* d_out, int out_size) {
    const float *x = nullptr, *W0 = nullptr, *b0 = nullptr, *W1 = nullptr;
    const float *b1 = nullptr, *W2 = nullptr, *b2 = nullptr;
    for (int idx = 0; idx < n_in; ++idx) {
        switch (in_sizes[idx]) {
            case 131072:  x  = (const float*)d_in[idx]; break;   // [8192,16]
            case 65536:   W0 = (const float*)d_in[idx]; break;   // [4096,16]
            case 4096:    b0 = (const float*)d_in[idx]; break;
            case 8388608: W1 = (const float*)d_in[idx]; break;   // [2048,4096]
            case 2048:    b1 = (const float*)d_in[idx]; break;
            case 32768:   W2 = (const float*)d_in[idx]; break;   // [16,2048]
            case 16:      b2 = (const float*)d_in[idx]; break;
            default: break;
        }
    }

    const int n = out_size / 16;

    // gather/dup weights + preset out = b2  (needs >= 131072 threads)
    gather_kernel<<<512, 256>>>(W0, b0, W1, b1, W2, b2, (float*)d_out, out_size);

    const int chunks = (n + 127) / 128;
    mlp_kernel<<<chunks * 8, 256>>>(x, (float*)d_out, n);
}